// round 2
// baseline (speedup 1.0000x reference)
#include <cuda_runtime.h>
#include <math.h>

#define NN 10000
#define EE 160000
#define LL 6
#define MAXDEG 384

// ------------- device scratch (no allocation allowed) -------------
__device__ float g_h[NN*128];
__device__ float g_xh[NN*512];        // permuted [n][c][head]
__device__ float g_al_e[EE*24];       // [e][l*4+h]
__device__ float g_al_s[NN*4];
__device__ float g_al_d[NN*4];
__device__ float g_M1[512];           // [k][c]
__device__ float g_c1[128];
__device__ float g_Bedge[128*24];
__device__ float g_Bsd[LL*128*8];     // [l][r][o] o<4 src, o>=4 dst
__device__ float g_PB[96];            // [k][j] k*24+j
__device__ float g_pbB[24];
__device__ float g_ales[24];
__device__ float g_sacc[5];
__device__ float g_spart[2500*5];
__device__ int   g_counts[NN];
__device__ int   g_rowptr[NN+1];
__device__ int   g_cursor[NN];
__device__ int   g_csrc[EE+NN];
__device__ int   g_ceid[EE+NN];

// ------------- init -------------
__global__ void k_zero(){
    int i = blockIdx.x*blockDim.x + threadIdx.x;
    if (i < NN) g_counts[i] = 0;
}

// ------------- folded weights -------------
__global__ void k_precompute(const float* __restrict__ vnfc, const float* __restrict__ vnf_w,
                             const float* __restrict__ vnf_b, const float* __restrict__ ea_w,
                             const float* __restrict__ ea_b,  const float* __restrict__ att1_w,
                             const float* __restrict__ att1_b,
                             const float* __restrict__ glw,  const float* __restrict__ gas,
                             const float* __restrict__ gad,  const float* __restrict__ glew,
                             const float* __restrict__ gae)
{
    int b = blockIdx.x, tid = threadIdx.x;
    if (b == 0) {
        __shared__ float vnf[128];
        if (tid < 128) {
            float a = vnf_b[tid];
            #pragma unroll
            for (int k = 0; k < 6; k++) a += vnfc[k]*vnf_w[k*128+tid];
            vnf[tid] = a;
        }
        __syncthreads();
        if (tid < 128) {
            float a = att1_b[tid];
            for (int r = 0; r < 128; r++) {
                a += ea_b[r]*att1_w[r*128+tid];
                a += vnf[r]*att1_w[(128+r)*128+tid];
            }
            g_c1[tid] = a;
        }
    } else if (b <= 4) {
        int idx = (b-1)*128 + tid;      // k*128+c
        int k = idx >> 7, c = idx & 127;
        float a = 0.f;
        for (int r = 0; r < 128; r++) a += ea_w[k*128+r]*att1_w[r*128+c];
        g_M1[idx] = a;
    } else if (b <= 28) {
        int j = b - 5, r = tid, l = j >> 2, h2 = j & 3;
        const float* W = glew + l*65536 + r*512 + h2*128;
        const float* A = gae  + l*512 + h2*128;
        float a = 0.f;
        for (int m = 0; m < 128; m++) a += W[m]*A[m];
        g_Bedge[r*24+j] = a;
    } else {
        int bp = b - 29, l = bp >> 3, o = bp & 7, r = tid;
        const float *W, *A;
        if (o < 4) { W = glw + l*65536 + r*512 + o*128;       A = gas + l*512 + o*128; }
        else       { int h2=o-4; W = glw + l*65536 + r*512 + h2*128; A = gad + l*512 + h2*128; }
        float a = 0.f;
        for (int m = 0; m < 128; m++) a += W[m]*A[m];
        g_Bsd[l*1024 + r*8 + o] = a;
    }
}

__global__ void k_pb(const float* __restrict__ ea_w, const float* __restrict__ ea_b){
    int t = threadIdx.x;
    if (t < 96) {
        int k = t / 24, j = t % 24;
        float a = 0.f;
        for (int r = 0; r < 128; r++) a += ea_w[k*128+r]*g_Bedge[r*24+j];
        g_PB[t] = a;
    } else if (t < 120) {
        int j = t - 96;
        float a = 0.f;
        for (int r = 0; r < 128; r++) a += ea_b[r]*g_Bedge[r*24+j];
        g_pbB[j] = a;
    }
}

// ------------- node embedding -------------
__global__ void k_node_embed(const float* __restrict__ x, const float* __restrict__ w,
                             const float* __restrict__ b){
    int idx = blockIdx.x*blockDim.x + threadIdx.x;
    if (idx >= NN*128) return;
    int n = idx >> 7, c = idx & 127;
    const float* xr = x + n*8;
    float a = b[c];
    #pragma unroll
    for (int k = 0; k < 8; k++) a += xr[k]*w[k*128+c];
    g_h[idx] = a;
}

// ------------- fused edge MLP (64 edges / block of 256) -------------
__global__ void k_edge(const float* __restrict__ edge_attr,
                       const float* __restrict__ att2_w, const float* __restrict__ att2_b,
                       const float* __restrict__ att3_w, const float* __restrict__ att3_b)
{
    __shared__ float a1T[128][68];
    __shared__ float w2s[16][68];
    __shared__ float attr_s[64][4];
    __shared__ float gate_s[64];
    int tid = threadIdx.x;
    int e0  = blockIdx.x*64;
    attr_s[tid>>2][tid&3] = edge_attr[e0*4 + tid];
    __syncthreads();
    {   // a1T[c][m] = relu(c1[c] + attr[m]·M1[:,c])
        int c = tid & 127, mb = (tid >> 7)*32;
        float m0 = g_M1[c], m1 = g_M1[128+c], m2 = g_M1[256+c], m3 = g_M1[384+c];
        float cc = g_c1[c];
        #pragma unroll 8
        for (int mm = 0; mm < 32; mm++) {
            int m = mb + mm;
            float z = cc + attr_s[m][0]*m0 + attr_s[m][1]*m1 + attr_s[m][2]*m2 + attr_s[m][3]*m3;
            a1T[c][m] = fmaxf(z, 0.f);
        }
    }
    int tx = tid & 15, ty = tid >> 4;
    float acc[4][4] = {};
    int lk = tid >> 4, ln = (tid & 15)*4;
    for (int k0 = 0; k0 < 128; k0 += 16) {
        *(float4*)&w2s[lk][ln] = *(const float4*)(att2_w + (k0+lk)*64 + ln);
        __syncthreads();
        #pragma unroll
        for (int kk = 0; kk < 16; kk++) {
            float4 a = *(const float4*)&a1T[k0+kk][ty*4];
            float4 w = *(const float4*)&w2s[kk][tx*4];
            acc[0][0] += a.x*w.x; acc[0][1] += a.x*w.y; acc[0][2] += a.x*w.z; acc[0][3] += a.x*w.w;
            acc[1][0] += a.y*w.x; acc[1][1] += a.y*w.y; acc[1][2] += a.y*w.z; acc[1][3] += a.y*w.w;
            acc[2][0] += a.z*w.x; acc[2][1] += a.z*w.y; acc[2][2] += a.z*w.z; acc[2][3] += a.z*w.w;
            acc[3][0] += a.w*w.x; acc[3][1] += a.w*w.y; acc[3][2] += a.w*w.z; acc[3][3] += a.w*w.w;
        }
        __syncthreads();
    }
    float b20 = att2_b[tx*4+0], b21 = att2_b[tx*4+1], b22 = att2_b[tx*4+2], b23 = att2_b[tx*4+3];
    float w30 = att3_w[tx*4+0], w31 = att3_w[tx*4+1], w32 = att3_w[tx*4+2], w33 = att3_w[tx*4+3];
    #pragma unroll
    for (int i = 0; i < 4; i++) {
        float p = fmaxf(acc[i][0]+b20,0.f)*w30 + fmaxf(acc[i][1]+b21,0.f)*w31
                + fmaxf(acc[i][2]+b22,0.f)*w32 + fmaxf(acc[i][3]+b23,0.f)*w33;
        #pragma unroll
        for (int off = 8; off; off >>= 1) p += __shfl_xor_sync(0xffffffffu, p, off);
        if (tx == 0) gate_s[ty*4+i] = p;
    }
    __syncthreads();
    if (tid < 64) gate_s[tid] = 1.f/(1.f + __expf(-(gate_s[tid] + att3_b[0])));
    __syncthreads();
    for (int t = tid; t < 64*24; t += 256) {
        int m = t / 24, j = t % 24;
        float g = gate_s[m];
        float v = g*(g_pbB[j] + attr_s[m][0]*g_PB[j]    + attr_s[m][1]*g_PB[24+j]
                              + attr_s[m][2]*g_PB[48+j] + attr_s[m][3]*g_PB[72+j]);
        g_al_e[(e0+m)*24 + j] = v;
    }
    if (tid == 0) {
        float s0=0,s1=0,s2=0,s3=0,s4=0;
        for (int m = 0; m < 64; m++) {
            float g = gate_s[m];
            s0 += g*attr_s[m][0]; s1 += g*attr_s[m][1];
            s2 += g*attr_s[m][2]; s3 += g*attr_s[m][3]; s4 += g;
        }
        float* sp = g_spart + blockIdx.x*5;
        sp[0]=s0; sp[1]=s1; sp[2]=s2; sp[3]=s3; sp[4]=s4;
    }
}

__global__ void k_sacc(){
    __shared__ float red[256];
    int tid = threadIdx.x;
    for (int comp = 0; comp < 5; comp++) {
        float s = 0.f;
        for (int i = tid; i < 2500; i += 256) s += g_spart[i*5+comp];
        red[tid] = s; __syncthreads();
        for (int off = 128; off; off >>= 1) { if (tid < off) red[tid] += red[tid+off]; __syncthreads(); }
        if (tid == 0) g_sacc[comp] = red[0];
        __syncthreads();
    }
}

__global__ void k_selfloop(){
    int t = threadIdx.x;
    if (t < 24) {
        float v = g_sacc[0]*g_PB[t]    + g_sacc[1]*g_PB[24+t] + g_sacc[2]*g_PB[48+t]
                + g_sacc[3]*g_PB[72+t] + g_sacc[4]*g_pbB[t];
        g_ales[t] = v*(1.0f/EE);
    }
}

// ------------- CSR build -------------
__global__ void k_count(const int* __restrict__ ei){
    int i = blockIdx.x*blockDim.x + threadIdx.x;
    if (i < EE)          atomicAdd(&g_counts[ei[EE+i]], 1);
    else if (i < EE+NN)  atomicAdd(&g_counts[i-EE], 1);
}

__global__ void k_scan(){
    __shared__ int part[1024];
    int tid = threadIdx.x;
    int base = tid*10;
    int loc[10]; int s = 0;
    #pragma unroll
    for (int i = 0; i < 10; i++) {
        int idx = base+i;
        int c = (idx < NN) ? g_counts[idx] : 0;
        loc[i] = s; s += c;
    }
    part[tid] = s;
    __syncthreads();
    for (int off = 1; off < 1024; off <<= 1) {
        int t = (tid >= off) ? part[tid-off] : 0;
        __syncthreads();
        part[tid] += t;
        __syncthreads();
    }
    int excl = part[tid] - s;
    #pragma unroll
    for (int i = 0; i < 10; i++) {
        int idx = base+i;
        if (idx < NN) { g_rowptr[idx] = excl + loc[i]; g_cursor[idx] = 0; }
    }
    if (tid == 1023) g_rowptr[NN] = part[1023];
}

__global__ void k_fill(const int* __restrict__ ei){
    int i = blockIdx.x*blockDim.x + threadIdx.x;
    if (i < EE) {
        int d = ei[EE+i];
        int pos = g_rowptr[d] + atomicAdd(&g_cursor[d], 1);
        g_csrc[pos] = ei[i]; g_ceid[pos] = i;
    } else if (i < EE+NN) {
        int nd = i - EE;
        int pos = g_rowptr[nd] + atomicAdd(&g_cursor[nd], 1);
        g_csrc[pos] = nd; g_ceid[pos] = i;     // eid>=EE marks self loop
    }
}

__global__ void k_sortseg(){
    int n = blockIdx.x*blockDim.x + threadIdx.x;
    if (n >= NN) return;
    int lo = g_rowptr[n], hi = g_rowptr[n+1];
    for (int i = lo+1; i < hi; i++) {
        int e = g_ceid[i], s = g_csrc[i]; int j = i-1;
        while (j >= lo && g_ceid[j] > e) { g_ceid[j+1]=g_ceid[j]; g_csrc[j+1]=g_csrc[j]; j--; }
        g_ceid[j+1] = e; g_csrc[j+1] = s;
    }
}

// ------------- per-layer GEMM: xh = h @ lw, stored [n][c][head] -------------
__global__ void k_xh(const float* __restrict__ W){
    __shared__ float As[16][68];
    __shared__ float Ws[16][68];
    int tid = threadIdx.x;
    int m0 = blockIdx.x*64, n0 = blockIdx.y*64;
    int tx = tid & 15, ty = tid >> 4;
    float acc[4][4] = {};
    int am = tid >> 2, ak = (tid & 3)*4;
    int wk = tid >> 4, wn = (tid & 15)*4;
    for (int k0 = 0; k0 < 128; k0 += 16) {
        int row = m0 + am;
        float4 av = (row < NN) ? *(const float4*)(g_h + row*128 + k0 + ak)
                               : make_float4(0.f,0.f,0.f,0.f);
        As[ak+0][am]=av.x; As[ak+1][am]=av.y; As[ak+2][am]=av.z; As[ak+3][am]=av.w;
        *(float4*)&Ws[wk][wn] = *(const float4*)(W + (k0+wk)*512 + n0 + wn);
        __syncthreads();
        #pragma unroll
        for (int kk = 0; kk < 16; kk++) {
            float4 a = *(const float4*)&As[kk][ty*4];
            float4 w = *(const float4*)&Ws[kk][tx*4];
            acc[0][0] += a.x*w.x; acc[0][1] += a.x*w.y; acc[0][2] += a.x*w.z; acc[0][3] += a.x*w.w;
            acc[1][0] += a.y*w.x; acc[1][1] += a.y*w.y; acc[1][2] += a.y*w.z; acc[1][3] += a.y*w.w;
            acc[2][0] += a.z*w.x; acc[2][1] += a.z*w.y; acc[2][2] += a.z*w.z; acc[2][3] += a.z*w.w;
            acc[3][0] += a.w*w.x; acc[3][1] += a.w*w.y; acc[3][2] += a.w*w.z; acc[3][3] += a.w*w.w;
        }
        __syncthreads();
    }
    #pragma unroll
    for (int i = 0; i < 4; i++) {
        int n = m0 + ty*4 + i;
        if (n >= NN) continue;
        #pragma unroll
        for (int j = 0; j < 4; j++) {
            int col = n0 + tx*4 + j;
            g_xh[n*512 + (col & 127)*4 + (col >> 7)] = acc[i][j];
        }
    }
}

// ------------- al_s / al_d (one warp per node) -------------
__global__ void k_alsd(int l){
    int gt = blockIdx.x*blockDim.x + threadIdx.x;
    int warp = gt >> 5, lane = gt & 31;
    if (warp >= NN) return;
    float hv[4];
    *(float4*)hv = *(const float4*)(g_h + warp*128 + lane*4);
    const float* B = g_Bsd + l*1024;
    float p[8] = {0,0,0,0,0,0,0,0};
    #pragma unroll
    for (int q = 0; q < 4; q++) {
        int r = lane*4 + q;
        const float* br = B + r*8;
        #pragma unroll
        for (int o = 0; o < 8; o++) p[o] += hv[q]*br[o];
    }
    #pragma unroll
    for (int off = 16; off; off >>= 1)
        #pragma unroll
        for (int o = 0; o < 8; o++) p[o] += __shfl_xor_sync(0xffffffffu, p[o], off);
    if (lane == 0) {
        #pragma unroll
        for (int o = 0; o < 4; o++) { g_al_s[warp*4+o] = p[o]; g_al_d[warp*4+o] = p[o+4]; }
    }
}

// ------------- fused softmax + aggregate + residual + LN (one block per node) -------------
__global__ void k_agg(int l, const float* __restrict__ gbias,
                      const float* __restrict__ lns, const float* __restrict__ lnb){
    __shared__ int   s_src[MAXDEG];
    __shared__ float s_ex[MAXDEG][4];
    __shared__ float red4[128][4];
    __shared__ float red[128];
    __shared__ int   s_info[2];
    int n = blockIdx.x, tid = threadIdx.x;
    if (tid == 0) {
        int lo = g_rowptr[n];
        s_info[0] = lo;
        s_info[1] = min(g_rowptr[n+1] - lo, MAXDEG);
    }
    __syncthreads();
    int row = s_info[0], deg = s_info[1];
    float ald[4];
    #pragma unroll
    for (int h = 0; h < 4; h++) ald[h] = g_al_d[n*4+h];

    // pass A: alpha + max
    float mx[4] = {-1e30f,-1e30f,-1e30f,-1e30f};
    for (int k = tid; k < deg; k += 128) {
        int eid = g_ceid[row+k];
        int s   = g_csrc[row+k];
        s_src[k] = s;
        const float* ale = (eid < EE) ? (g_al_e + eid*24 + l*4) : (g_ales + l*4);
        #pragma unroll
        for (int h = 0; h < 4; h++) {
            float a = g_al_s[s*4+h] + ald[h] + ale[h];
            a = (a > 0.f) ? a : 0.2f*a;
            s_ex[k][h] = a;
            mx[h] = fmaxf(mx[h], a);
        }
    }
    #pragma unroll
    for (int h = 0; h < 4; h++) red4[tid][h] = mx[h];
    __syncthreads();
    for (int off = 64; off; off >>= 1) {
        if (tid < off) {
            #pragma unroll
            for (int h = 0; h < 4; h++) red4[tid][h] = fmaxf(red4[tid][h], red4[tid+off][h]);
        }
        __syncthreads();
    }
    float smx[4];
    #pragma unroll
    for (int h = 0; h < 4; h++) smx[h] = red4[0][h];
    __syncthreads();

    // pass B: exp + sum
    float sm[4] = {0,0,0,0};
    for (int k = tid; k < deg; k += 128) {
        #pragma unroll
        for (int h = 0; h < 4; h++) {
            float e = __expf(s_ex[k][h] - smx[h]);
            s_ex[k][h] = e;
            sm[h] += e;
        }
    }
    #pragma unroll
    for (int h = 0; h < 4; h++) red4[tid][h] = sm[h];
    __syncthreads();
    for (int off = 64; off; off >>= 1) {
        if (tid < off) {
            #pragma unroll
            for (int h = 0; h < 4; h++) red4[tid][h] += red4[tid+off][h];
        }
        __syncthreads();
    }
    float inv[4];
    #pragma unroll
    for (int h = 0; h < 4; h++) inv[h] = 1.f/(red4[0][h] + 1e-16f);
    __syncthreads();

    // pass C: weighted gather (channel = tid)
    int c = tid;
    float a0=0.f, a1=0.f, a2=0.f, a3=0.f;
    for (int k = 0; k < deg; k++) {
        int s = s_src[k];
        float4 xv = *(const float4*)(g_xh + s*512 + c*4);
        float4 w  = *(const float4*)&s_ex[k][0];
        a0 += w.x*xv.x; a1 += w.y*xv.y; a2 += w.z*xv.z; a3 += w.w*xv.w;
    }
    float hc = 0.25f*(a0*inv[0] + a1*inv[1] + a2*inv[2] + a3*inv[3]) + gbias[c];
    float v  = g_h[n*128 + c] + fmaxf(hc, 0.f);

    // LayerNorm over 128 channels
    red[tid] = v; __syncthreads();
    for (int off = 64; off; off >>= 1) { if (tid < off) red[tid] += red[tid+off]; __syncthreads(); }
    float mean = red[0]*(1.f/128.f);
    __syncthreads();
    float d = v - mean;
    red[tid] = d*d; __syncthreads();
    for (int off = 64; off; off >>= 1) { if (tid < off) red[tid] += red[tid+off]; __syncthreads(); }
    float var = red[0]*(1.f/128.f);
    g_h[n*128 + c] = d*rsqrtf(var + 1e-5f)*lns[c] + lnb[c];
}

// ------------- output projection -------------
__global__ void k_out(const float* __restrict__ W, const float* __restrict__ b,
                      float* __restrict__ out){
    __shared__ float As[16][68];
    __shared__ float Ws[16][68];
    int tid = threadIdx.x;
    int m0 = blockIdx.x*64, n0 = blockIdx.y*64;
    int tx = tid & 15, ty = tid >> 4;
    float acc[4][4] = {};
    int am = tid >> 2, ak = (tid & 3)*4;
    int wk = tid >> 4, wn = (tid & 15)*4;
    for (int k0 = 0; k0 < 128; k0 += 16) {
        int row = m0 + am;
        float4 av = (row < NN) ? *(const float4*)(g_h + row*128 + k0 + ak)
                               : make_float4(0.f,0.f,0.f,0.f);
        As[ak+0][am]=av.x; As[ak+1][am]=av.y; As[ak+2][am]=av.z; As[ak+3][am]=av.w;
        *(float4*)&Ws[wk][wn] = *(const float4*)(W + (k0+wk)*256 + n0 + wn);
        __syncthreads();
        #pragma unroll
        for (int kk = 0; kk < 16; kk++) {
            float4 a = *(const float4*)&As[kk][ty*4];
            float4 w = *(const float4*)&Ws[kk][tx*4];
            acc[0][0] += a.x*w.x; acc[0][1] += a.x*w.y; acc[0][2] += a.x*w.z; acc[0][3] += a.x*w.w;
            acc[1][0] += a.y*w.x; acc[1][1] += a.y*w.y; acc[1][2] += a.y*w.z; acc[1][3] += a.y*w.w;
            acc[2][0] += a.z*w.x; acc[2][1] += a.z*w.y; acc[2][2] += a.z*w.z; acc[2][3] += a.z*w.w;
            acc[3][0] += a.w*w.x; acc[3][1] += a.w*w.y; acc[3][2] += a.w*w.z; acc[3][3] += a.w*w.w;
        }
        __syncthreads();
    }
    #pragma unroll
    for (int i = 0; i < 4; i++) {
        int n = m0 + ty*4 + i;
        if (n >= NN) continue;
        #pragma unroll
        for (int j = 0; j < 4; j++) {
            int col = n0 + tx*4 + j;
            out[n*256 + col] = acc[i][j] + b[col];
        }
    }
}

// ------------- launch -------------
extern "C" void kernel_launch(void* const* d_in, const int* in_sizes, int n_in,
                              void* d_out, int out_size) {
    const float* x       = (const float*)d_in[0];
    const int*   ei      = (const int*)  d_in[1];
    const float* e_attr  = (const float*)d_in[2];
    const float* vnfc    = (const float*)d_in[3];
    const float* node_w  = (const float*)d_in[4];
    const float* node_b  = (const float*)d_in[5];
    const float* ea_w    = (const float*)d_in[6];
    const float* ea_b    = (const float*)d_in[7];
    const float* vnf_w   = (const float*)d_in[8];
    const float* vnf_b   = (const float*)d_in[9];
    const float* att1_w  = (const float*)d_in[10];
    const float* att1_b  = (const float*)d_in[11];
    const float* att2_w  = (const float*)d_in[12];
    const float* att2_b  = (const float*)d_in[13];
    const float* att3_w  = (const float*)d_in[14];
    const float* att3_b  = (const float*)d_in[15];
    const float* glw     = (const float*)d_in[16];
    const float* gas     = (const float*)d_in[17];
    const float* gad     = (const float*)d_in[18];
    const float* glew    = (const float*)d_in[19];
    const float* gae     = (const float*)d_in[20];
    const float* gbias   = (const float*)d_in[21];
    const float* lns     = (const float*)d_in[22];
    const float* lnb     = (const float*)d_in[23];
    const float* out_w   = (const float*)d_in[24];
    const float* out_b   = (const float*)d_in[25];
    float* out = (float*)d_out;

    k_zero<<<(NN+255)/256, 256>>>();
    k_precompute<<<77, 128>>>(vnfc, vnf_w, vnf_b, ea_w, ea_b, att1_w, att1_b,
                              glw, gas, gad, glew, gae);
    k_pb<<<1, 128>>>(ea_w, ea_b);
    k_node_embed<<<(NN*128+255)/256, 256>>>(x, node_w, node_b);
    k_edge<<<EE/64, 256>>>(e_attr, att2_w, att2_b, att3_w, att3_b);
    k_sacc<<<1, 256>>>();
    k_selfloop<<<1, 32>>>();
    k_count<<<(EE+NN+255)/256, 256>>>(ei);
    k_scan<<<1, 1024>>>();
    k_fill<<<(EE+NN+255)/256, 256>>>(ei);
    k_sortseg<<<(NN+255)/256, 256>>>();

    for (int l = 0; l < LL; l++) {
        k_xh<<<dim3(157, 8), 256>>>(glw + (size_t)l*128*512);
        k_alsd<<<1250, 256>>>(l);
        k_agg<<<NN, 128>>>(l, gbias + l*128, lns + l*128, lnb + l*128);
    }
    k_out<<<dim3(157, 4), 256>>>(out_w, out_b, out);
}